// round 3
// baseline (speedup 1.0000x reference)
#include <cuda_runtime.h>
#include <math.h>

// Shapes: B=64 (seq), T=256 (batch, only t=255 matters), D=H=1024, C=27.
#define STEPS 64
#define HID   1024
#define G4    4096
#define TT    256
#define DD    1024
#define CC    27
#define NB    128   // recurrence CTAs (all co-resident on 148 SMs)

// ---- scratch (device globals; no allocation) ----
__device__ float g_xg[STEPS * G4];   // gate preactivations (input part), reused by both layers
__device__ float g_h1[STEPS * HID];  // layer-1 hidden sequence
__device__ float g_h2[STEPS * HID];  // layer-2 hidden sequence
__device__ float g_z [STEPS * 512];  // fc1 output
__device__ int   g_ctr[128];         // grid-barrier counters (layer0: [0..63), layer1: [64..128))

__global__ void reset_kernel() {
    if (threadIdx.x < 128) g_ctr[threadIdx.x] = 0;
}

__device__ __forceinline__ float sigf(float x) { return 1.0f / (1.0f + __expf(-x)); }

// ============================================================
// Tiled GEMM: out[s][row] = sum_k X[s][k]*W[row][k] + bias (+relu)
//   mode 0: X = x[:,255,:] (stride T*D), out=g_xg, rows=4096, bias=ba+bb
//   mode 1: X = g_h1,                    out=g_xg, rows=4096, bias=ba+bb
//   mode 2: X = g_h2,                    out=g_z,  rows=512,  bias=ba, relu
// grid = rows/32 blocks, 128 threads, thread tile 4 rows x 4 cols (64 s total)
// ============================================================
__global__ __launch_bounds__(128)
void gemm_k(int mode, const float* __restrict__ xin,
            const float* __restrict__ W,
            const float* __restrict__ ba, const float* __restrict__ bb)
{
    __shared__ __align__(16) float Ws[32][36];
    __shared__ __align__(16) float Xs[32][68];

    const float* X;
    long xbase, xstride;
    float* out;
    int nrows;
    if (mode == 0)      { X = xin;  xbase = 255L * DD; xstride = (long)TT * DD; out = g_xg; nrows = G4;  }
    else if (mode == 1) { X = g_h1; xbase = 0;         xstride = HID;           out = g_xg; nrows = G4;  }
    else                { X = g_h2; xbase = 0;         xstride = HID;           out = g_z;  nrows = 512; }

    const int t  = threadIdx.x;
    const int rb = blockIdx.x * 32;
    const int tr = t >> 4;   // 0..7  -> rows tr*4 .. tr*4+3
    const int tc = t & 15;   // 0..15 -> cols tc*4 .. tc*4+3

    float acc[4][4];
#pragma unroll
    for (int i = 0; i < 4; i++)
#pragma unroll
        for (int j = 0; j < 4; j++) acc[i][j] = 0.0f;

    for (int kt = 0; kt < 1024; kt += 32) {
        // cooperative load W tile (32 rows x 32 k), transposed into Ws[k][r]
#pragma unroll
        for (int i = 0; i < 8; i++) {
            int e = t + i * 128;
            int r = e >> 5, k = e & 31;
            Ws[k][r] = W[(long)(rb + r) * 1024 + kt + k];
        }
        // cooperative load X tile (64 s x 32 k), transposed into Xs[k][s]
#pragma unroll
        for (int i = 0; i < 16; i++) {
            int e = t + i * 128;
            int s = e >> 5, k = e & 31;
            Xs[k][s] = X[xbase + (long)s * xstride + kt + k];
        }
        __syncthreads();
#pragma unroll
        for (int k = 0; k < 32; k++) {
            float4 wv = *(const float4*)&Ws[k][tr * 4];
            float4 xv = *(const float4*)&Xs[k][tc * 4];
            acc[0][0] = fmaf(wv.x, xv.x, acc[0][0]);
            acc[0][1] = fmaf(wv.x, xv.y, acc[0][1]);
            acc[0][2] = fmaf(wv.x, xv.z, acc[0][2]);
            acc[0][3] = fmaf(wv.x, xv.w, acc[0][3]);
            acc[1][0] = fmaf(wv.y, xv.x, acc[1][0]);
            acc[1][1] = fmaf(wv.y, xv.y, acc[1][1]);
            acc[1][2] = fmaf(wv.y, xv.z, acc[1][2]);
            acc[1][3] = fmaf(wv.y, xv.w, acc[1][3]);
            acc[2][0] = fmaf(wv.z, xv.x, acc[2][0]);
            acc[2][1] = fmaf(wv.z, xv.y, acc[2][1]);
            acc[2][2] = fmaf(wv.z, xv.z, acc[2][2]);
            acc[2][3] = fmaf(wv.z, xv.w, acc[2][3]);
            acc[3][0] = fmaf(wv.w, xv.x, acc[3][0]);
            acc[3][1] = fmaf(wv.w, xv.y, acc[3][1]);
            acc[3][2] = fmaf(wv.w, xv.z, acc[3][2]);
            acc[3][3] = fmaf(wv.w, xv.w, acc[3][3]);
        }
        __syncthreads();
    }

#pragma unroll
    for (int i = 0; i < 4; i++) {
        int row = rb + tr * 4 + i;
        float bv = ba[row] + (mode < 2 ? bb[row] : 0.0f);
#pragma unroll
        for (int j = 0; j < 4; j++) {
            int s = tc * 4 + j;
            float v = acc[i][j] + bv;
            if (mode == 2) v = fmaxf(v, 0.0f);
            out[(long)s * nrows + row] = v;
        }
    }
}

// ============================================================
// Persistent LSTM recurrence. 128 CTAs x 256 threads.
// CTA r owns hidden units j in [8r, 8r+8). Warp w: gate g=w&3,
// row quad jh=w>>2 -> rows (g*1024 + 8r + jh*4 + q), q=0..3.
// Whh rows live in registers (128 floats/thread).
// Grid barrier per step via pre-zeroed counters.
// ============================================================
__global__ __launch_bounds__(256, 1)
void lstm_rec(const float* __restrict__ Whh, int layer)
{
    __shared__ __align__(16) float hsh[HID];
    __shared__ float gb[8][4];
    __shared__ float cst[8];

    float* hseq = layer ? g_h2 : g_h1;
    const int r    = blockIdx.x;
    const int t    = threadIdx.x;
    const int lane = t & 31;
    const int w    = t >> 5;
    const int g    = w & 3;
    const int jh   = w >> 2;
    const int rowbase = (g << 10) + (r << 3) + (jh << 2);
    const int cbase   = layer * 64;

    // load 4 Whh rows into registers: lane covers columns lane, lane+32, ...
    float wr0[32], wr1[32], wr2[32], wr3[32];
#pragma unroll
    for (int k = 0; k < 32; k++) {
        long o = (long)rowbase * 1024 + k * 32 + lane;
        wr0[k] = Whh[o];
        wr1[k] = Whh[o + 1024];
        wr2[k] = Whh[o + 2048];
        wr3[k] = Whh[o + 3072];
    }
    if (t < 8) cst[t] = 0.0f;
    __syncthreads();

    for (int s = 0; s < STEPS; s++) {
        // prefetch input-gate contributions (lane 0 per warp)
        float xq0 = 0.f, xq1 = 0.f, xq2 = 0.f, xq3 = 0.f;
        if (lane == 0) {
            const float* xp = &g_xg[s * G4 + rowbase];
            xq0 = xp[0]; xq1 = xp[1]; xq2 = xp[2]; xq3 = xp[3];
        }

        float a0 = 0.f, a1 = 0.f, a2 = 0.f, a3 = 0.f;
        if (s > 0) {
            // stage h_{s-1} into smem (bypass L1: written by other SMs)
            float4 hv = __ldcg((const float4*)(hseq + (s - 1) * HID) + t);
            ((float4*)hsh)[t] = hv;
            __syncthreads();
#pragma unroll
            for (int k = 0; k < 32; k++) {
                float hk = hsh[k * 32 + lane];
                a0 = fmaf(wr0[k], hk, a0);
                a1 = fmaf(wr1[k], hk, a1);
                a2 = fmaf(wr2[k], hk, a2);
                a3 = fmaf(wr3[k], hk, a3);
            }
        }
#pragma unroll
        for (int o = 16; o > 0; o >>= 1) {
            a0 += __shfl_down_sync(0xffffffffu, a0, o);
            a1 += __shfl_down_sync(0xffffffffu, a1, o);
            a2 += __shfl_down_sync(0xffffffffu, a2, o);
            a3 += __shfl_down_sync(0xffffffffu, a3, o);
        }
        if (lane == 0) {
            gb[jh * 4 + 0][g] = a0 + xq0;
            gb[jh * 4 + 1][g] = a1 + xq1;
            gb[jh * 4 + 2][g] = a2 + xq2;
            gb[jh * 4 + 3][g] = a3 + xq3;
        }
        __syncthreads();

        if (t < 8) {
            float iv = gb[t][0], fv = gb[t][1], gv = gb[t][2], ov = gb[t][3];
            float c = sigf(fv) * cst[t] + sigf(iv) * tanhf(gv);
            cst[t] = c;
            float h = sigf(ov) * tanhf(c);
            hseq[s * HID + r * 8 + t] = h;
            __threadfence();
        }
        __syncthreads();

        if (s < STEPS - 1) {
            if (t == 0) {
                atomicAdd(&g_ctr[cbase + s], 1);
                volatile int* p = &g_ctr[cbase + s];
                while (*p < NB) { }
                __threadfence();
            }
            __syncthreads();
        }
    }
}

// ============================================================
// FC2: out[s][c] = z[s] . W2[c] + b2[c]   (64 x 27, K=512)
// ============================================================
__global__ __launch_bounds__(128)
void fc2_k(const float* __restrict__ W2, const float* __restrict__ b2,
           float* __restrict__ out)
{
    __shared__ __align__(16) float zsh[512];
    const int s = blockIdx.x;
    const int t = threadIdx.x, lane = t & 31, w = t >> 5;
    ((float4*)zsh)[t] = *((const float4*)(g_z + s * 512) + t);
    __syncthreads();
    for (int c = w; c < CC; c += 4) {
        float acc = 0.f;
#pragma unroll
        for (int k = 0; k < 16; k++)
            acc = fmaf(zsh[k * 32 + lane], W2[c * 512 + k * 32 + lane], acc);
#pragma unroll
        for (int o = 16; o > 0; o >>= 1)
            acc += __shfl_down_sync(0xffffffffu, acc, o);
        if (lane == 0) out[s * CC + c] = acc + b2[c];
    }
}

// ============================================================
extern "C" void kernel_launch(void* const* d_in, const int* in_sizes, int n_in,
                              void* d_out, int out_size)
{
    const float* x    = (const float*)d_in[0];
    const float* Wih0 = (const float*)d_in[1];
    const float* Whh0 = (const float*)d_in[2];
    const float* bih0 = (const float*)d_in[3];
    const float* bhh0 = (const float*)d_in[4];
    const float* Wih1 = (const float*)d_in[5];
    const float* Whh1 = (const float*)d_in[6];
    const float* bih1 = (const float*)d_in[7];
    const float* bhh1 = (const float*)d_in[8];
    const float* W1   = (const float*)d_in[9];
    const float* b1   = (const float*)d_in[10];
    const float* W2   = (const float*)d_in[11];
    const float* b2   = (const float*)d_in[12];
    float* out = (float*)d_out;

    reset_kernel<<<1, 128>>>();
    gemm_k<<<128, 128>>>(0, x, Wih0, bih0, bhh0);          // xg for layer 1
    lstm_rec<<<NB, 256>>>(Whh0, 0);                        // layer-1 recurrence
    gemm_k<<<128, 128>>>(1, nullptr, Wih1, bih1, bhh1);    // xg for layer 2
    lstm_rec<<<NB, 256>>>(Whh1, 1);                        // layer-2 recurrence
    gemm_k<<<16, 128>>>(2, nullptr, W1, b1, b1);           // fc1 + relu
    fc2_k<<<64, 128>>>(W2, b2, out);                       // fc2
}

// round 4
// speedup vs baseline: 1.1626x; 1.1626x over previous
#include <cuda_runtime.h>
#include <math.h>

// Shapes: B=64 (seq), T=256 (batch, only t=255 matters), D=H=1024, C=27.
#define STEPS 64
#define HID   1024
#define G4    4096
#define TT    256
#define DD    1024
#define CC    27
#define NB    128   // recurrence CTAs (all co-resident, 1/SM)

// ---- scratch (device globals; no allocation) ----
__device__ float g_xgp[4L * STEPS * G4];  // GEMM partials (4 K-chunks)
__device__ float g_xg [STEPS * G4];       // reduced gate preactivations
__device__ float g_h1 [STEPS * HID];
__device__ float g_h2 [STEPS * HID];
__device__ float g_zp [4 * STEPS * 512];  // fc1 partials
__device__ int   g_ctr[128];              // barrier counters (layer0: 0..63, layer1: 64..127)

__global__ void reset_kernel() {
    if (threadIdx.x < 128) g_ctr[threadIdx.x] = 0;
}

__device__ __forceinline__ float sigf(float x) { return 1.0f / (1.0f + __expf(-x)); }

__device__ __forceinline__ void red_release_add(int* p) {
    asm volatile("red.release.gpu.global.add.s32 [%0], %1;" :: "l"(p), "r"(1) : "memory");
}
__device__ __forceinline__ int ld_acquire(const int* p) {
    int v;
    asm volatile("ld.acquire.gpu.global.s32 %0, [%1];" : "=r"(v) : "l"(p) : "memory");
    return v;
}

// ============================================================
// K-split tiled GEMM (partials only, no bias):
//   mode 0: X = x[:,255,:] (stride T*D), rows=4096 -> g_xgp
//   mode 1: X = g_h1,                    rows=4096 -> g_xgp
//   mode 2: X = g_h2,                    rows=512  -> g_zp
// grid = (rows/32) * 4 chunks, 128 threads, thread tile 4x4.
// ============================================================
__global__ __launch_bounds__(128)
void gemm4_k(int mode, const float* __restrict__ xin, const float* __restrict__ W)
{
    __shared__ __align__(16) float Ws[32][36];
    __shared__ __align__(16) float Xs[32][68];

    const float* X;
    long xbase, xstride;
    float* pout;
    int nrows, ntiles;
    if (mode == 0)      { X = xin;  xbase = 255L * DD; xstride = (long)TT * DD; pout = g_xgp; nrows = G4;  ntiles = 128; }
    else if (mode == 1) { X = g_h1; xbase = 0;         xstride = HID;           pout = g_xgp; nrows = G4;  ntiles = 128; }
    else                { X = g_h2; xbase = 0;         xstride = HID;           pout = g_zp;  nrows = 512; ntiles = 16;  }

    const int chunk = blockIdx.x / ntiles;
    const int rb    = (blockIdx.x % ntiles) * 32;
    pout += (long)chunk * STEPS * nrows;

    const int t  = threadIdx.x;
    const int tr = t >> 4;   // 0..7
    const int tc = t & 15;   // 0..15

    float acc[4][4];
#pragma unroll
    for (int i = 0; i < 4; i++)
#pragma unroll
        for (int j = 0; j < 4; j++) acc[i][j] = 0.0f;

    const int k0 = chunk * 256;
    for (int kt = k0; kt < k0 + 256; kt += 32) {
#pragma unroll
        for (int i = 0; i < 8; i++) {
            int e = t + i * 128;
            int r = e >> 5, k = e & 31;
            Ws[k][r] = W[(long)(rb + r) * 1024 + kt + k];
        }
#pragma unroll
        for (int i = 0; i < 16; i++) {
            int e = t + i * 128;
            int s = e >> 5, k = e & 31;
            Xs[k][s] = X[xbase + (long)s * xstride + kt + k];
        }
        __syncthreads();
#pragma unroll
        for (int k = 0; k < 32; k++) {
            float4 wv = *(const float4*)&Ws[k][tr * 4];
            float4 xv = *(const float4*)&Xs[k][tc * 4];
            acc[0][0] = fmaf(wv.x, xv.x, acc[0][0]);
            acc[0][1] = fmaf(wv.x, xv.y, acc[0][1]);
            acc[0][2] = fmaf(wv.x, xv.z, acc[0][2]);
            acc[0][3] = fmaf(wv.x, xv.w, acc[0][3]);
            acc[1][0] = fmaf(wv.y, xv.x, acc[1][0]);
            acc[1][1] = fmaf(wv.y, xv.y, acc[1][1]);
            acc[1][2] = fmaf(wv.y, xv.z, acc[1][2]);
            acc[1][3] = fmaf(wv.y, xv.w, acc[1][3]);
            acc[2][0] = fmaf(wv.z, xv.x, acc[2][0]);
            acc[2][1] = fmaf(wv.z, xv.y, acc[2][1]);
            acc[2][2] = fmaf(wv.z, xv.z, acc[2][2]);
            acc[2][3] = fmaf(wv.z, xv.w, acc[2][3]);
            acc[3][0] = fmaf(wv.w, xv.x, acc[3][0]);
            acc[3][1] = fmaf(wv.w, xv.y, acc[3][1]);
            acc[3][2] = fmaf(wv.w, xv.z, acc[3][2]);
            acc[3][3] = fmaf(wv.w, xv.w, acc[3][3]);
        }
        __syncthreads();
    }

#pragma unroll
    for (int i = 0; i < 4; i++) {
        int row = rb + tr * 4 + i;
#pragma unroll
        for (int j = 0; j < 4; j++) {
            int s = tc * 4 + j;
            pout[(long)s * nrows + row] = acc[i][j];
        }
    }
}

// ============================================================
// Reduce 4 GEMM partials + (ba+bb) bias -> g_xg. 256x256 thr, float4/thread.
// ============================================================
__global__ __launch_bounds__(256)
void reduce_bias_k(const float* __restrict__ ba, const float* __restrict__ bb)
{
    const int i4 = blockIdx.x * 256 + threadIdx.x;     // 0..65535
    const long base = (long)i4 * 4;
    const int row = (int)(base & 4095);
    float4 p0 = *(const float4*)&g_xgp[base];
    float4 p1 = *(const float4*)&g_xgp[base + 1L * STEPS * G4];
    float4 p2 = *(const float4*)&g_xgp[base + 2L * STEPS * G4];
    float4 p3 = *(const float4*)&g_xgp[base + 3L * STEPS * G4];
    float4 va = *(const float4*)&ba[row];
    float4 vb = *(const float4*)&bb[row];
    float4 o;
    o.x = p0.x + p1.x + p2.x + p3.x + va.x + vb.x;
    o.y = p0.y + p1.y + p2.y + p3.y + va.y + vb.y;
    o.z = p0.z + p1.z + p2.z + p3.z + va.z + vb.z;
    o.w = p0.w + p1.w + p2.w + p3.w + va.w + vb.w;
    *(float4*)&g_xg[base] = o;
}

// ============================================================
// Persistent LSTM recurrence. 128 CTAs x 256 threads, weights in regs.
// Grid barrier: red.release + ld.acquire on pre-zeroed counters.
// ============================================================
__global__ __launch_bounds__(256, 1)
void lstm_rec(const float* __restrict__ Whh, int layer)
{
    __shared__ __align__(16) float hsh[HID];
    __shared__ float gb[8][4];
    __shared__ float cst[8];

    float* hseq = layer ? g_h2 : g_h1;
    const int r    = blockIdx.x;
    const int t    = threadIdx.x;
    const int lane = t & 31;
    const int w    = t >> 5;
    const int g    = w & 3;
    const int jh   = w >> 2;
    const int rowbase = (g << 10) + (r << 3) + (jh << 2);
    const int cbase   = layer * 64;

    float wr0[32], wr1[32], wr2[32], wr3[32];
#pragma unroll
    for (int k = 0; k < 32; k++) {
        long o = (long)rowbase * 1024 + k * 32 + lane;
        wr0[k] = Whh[o];
        wr1[k] = Whh[o + 1024];
        wr2[k] = Whh[o + 2048];
        wr3[k] = Whh[o + 3072];
    }
    if (t < 8) cst[t] = 0.0f;
    __syncthreads();

    for (int s = 0; s < STEPS; s++) {
        float4 xq = make_float4(0.f, 0.f, 0.f, 0.f);
        if (lane == 0) xq = *(const float4*)&g_xg[s * G4 + rowbase];

        float a0 = 0.f, a1 = 0.f, a2 = 0.f, a3 = 0.f;
        if (s > 0) {
            float4 hv = __ldcg((const float4*)(hseq + (s - 1) * HID) + t);
            ((float4*)hsh)[t] = hv;
            __syncthreads();
#pragma unroll
            for (int k = 0; k < 32; k++) {
                float hk = hsh[k * 32 + lane];
                a0 = fmaf(wr0[k], hk, a0);
                a1 = fmaf(wr1[k], hk, a1);
                a2 = fmaf(wr2[k], hk, a2);
                a3 = fmaf(wr3[k], hk, a3);
            }
        }
#pragma unroll
        for (int o = 16; o > 0; o >>= 1) {
            a0 += __shfl_down_sync(0xffffffffu, a0, o);
            a1 += __shfl_down_sync(0xffffffffu, a1, o);
            a2 += __shfl_down_sync(0xffffffffu, a2, o);
            a3 += __shfl_down_sync(0xffffffffu, a3, o);
        }
        if (lane == 0) {
            gb[jh * 4 + 0][g] = a0 + xq.x;
            gb[jh * 4 + 1][g] = a1 + xq.y;
            gb[jh * 4 + 2][g] = a2 + xq.z;
            gb[jh * 4 + 3][g] = a3 + xq.w;
        }
        __syncthreads();

        if (t < 8) {
            float iv = gb[t][0], fv = gb[t][1], gv = gb[t][2], ov = gb[t][3];
            float c = sigf(fv) * cst[t] + sigf(iv) * tanhf(gv);
            cst[t] = c;
            hseq[s * HID + r * 8 + t] = sigf(ov) * tanhf(c);
        }
        __syncthreads();                    // h stores done CTA-wide

        if (s < STEPS - 1) {
            if (t == 0) {
                int* ctr = &g_ctr[cbase + s];
                red_release_add(ctr);       // release: h stores visible before count
                while (ld_acquire(ctr) < NB) { }
            }
            __syncthreads();                // broadcast arrival to whole CTA
        }
    }
}

// ============================================================
// FC2 fused with fc1 partial-reduce + bias + ReLU.
// One CTA per s (64), 128 threads.
// ============================================================
__global__ __launch_bounds__(128)
void fc2_k(const float* __restrict__ W2, const float* __restrict__ b2,
           const float* __restrict__ b1, float* __restrict__ out)
{
    __shared__ __align__(16) float zsh[512];
    const int s = blockIdx.x;
    const int t = threadIdx.x, lane = t & 31, w = t >> 5;

    {
        const long base = (long)s * 512 + t * 4;
        float4 p0 = *(const float4*)&g_zp[base];
        float4 p1 = *(const float4*)&g_zp[base + 1L * STEPS * 512];
        float4 p2 = *(const float4*)&g_zp[base + 2L * STEPS * 512];
        float4 p3 = *(const float4*)&g_zp[base + 3L * STEPS * 512];
        float4 vb = *(const float4*)&b1[t * 4];
        float4 z;
        z.x = fmaxf(p0.x + p1.x + p2.x + p3.x + vb.x, 0.f);
        z.y = fmaxf(p0.y + p1.y + p2.y + p3.y + vb.y, 0.f);
        z.z = fmaxf(p0.z + p1.z + p2.z + p3.z + vb.z, 0.f);
        z.w = fmaxf(p0.w + p1.w + p2.w + p3.w + vb.w, 0.f);
        *(float4*)&zsh[t * 4] = z;
    }
    __syncthreads();

    for (int c = w; c < CC; c += 4) {
        float acc = 0.f;
#pragma unroll
        for (int k = 0; k < 16; k++)
            acc = fmaf(zsh[k * 32 + lane], W2[c * 512 + k * 32 + lane], acc);
#pragma unroll
        for (int o = 16; o > 0; o >>= 1)
            acc += __shfl_down_sync(0xffffffffu, acc, o);
        if (lane == 0) out[s * CC + c] = acc + b2[c];
    }
}

// ============================================================
extern "C" void kernel_launch(void* const* d_in, const int* in_sizes, int n_in,
                              void* d_out, int out_size)
{
    const float* x    = (const float*)d_in[0];
    const float* Wih0 = (const float*)d_in[1];
    const float* Whh0 = (const float*)d_in[2];
    const float* bih0 = (const float*)d_in[3];
    const float* bhh0 = (const float*)d_in[4];
    const float* Wih1 = (const float*)d_in[5];
    const float* Whh1 = (const float*)d_in[6];
    const float* bih1 = (const float*)d_in[7];
    const float* bhh1 = (const float*)d_in[8];
    const float* W1   = (const float*)d_in[9];
    const float* b1   = (const float*)d_in[10];
    const float* W2   = (const float*)d_in[11];
    const float* b2   = (const float*)d_in[12];
    float* out = (float*)d_out;

    reset_kernel<<<1, 128>>>();
    gemm4_k<<<512, 128>>>(0, x, Wih0);          // xg partials, layer 1
    reduce_bias_k<<<256, 256>>>(bih0, bhh0);
    lstm_rec<<<NB, 256>>>(Whh0, 0);
    gemm4_k<<<512, 128>>>(1, nullptr, Wih1);    // xg partials, layer 2
    reduce_bias_k<<<256, 256>>>(bih1, bhh1);
    lstm_rec<<<NB, 256>>>(Whh1, 1);
    gemm4_k<<<64, 128>>>(2, nullptr, W1);       // fc1 partials
    fc2_k<<<64, 128>>>(W2, b2, b1, out);        // reduce+relu+fc2
}